// round 5
// baseline (speedup 1.0000x reference)
#include <cuda_runtime.h>
#include <cuda_fp16.h>
#include <cstdint>
#include <cstddef>

// Problem dims
#define D1 64
#define D2 64
#define BB 32
#define II 64
#define OO 128
#define M_TOT (D1 * D2 * BB)   // 131072
#define NPRE  640              // 5 gates * 128

// Scratch: pre-activations [m=(d1,d2,b)][g*128+o] as fp16, bias folded in.
__device__ __half g_preh[(size_t)M_TOT * NPRE];

// ========================= helpers =========================
__device__ __forceinline__ uint32_t smem_u32(const void* p) {
    uint32_t a;
    asm("{ .reg .u64 t; cvta.to.shared.u64 t, %1; cvt.u32.u64 %0, t; }"
        : "=r"(a) : "l"(p));
    return a;
}

__device__ __forceinline__ void ldsm_x4(uint32_t& r0, uint32_t& r1,
                                        uint32_t& r2, uint32_t& r3,
                                        uint32_t addr) {
    asm volatile("ldmatrix.sync.aligned.m8n8.x4.shared.b16 {%0,%1,%2,%3}, [%4];"
                 : "=r"(r0), "=r"(r1), "=r"(r2), "=r"(r3) : "r"(addr));
}

// D += A * B  (m16n8k16, fp16 in, f32 accum)
__device__ __forceinline__ void mma_f16(float* d, const uint32_t* a,
                                        uint32_t b0, uint32_t b1) {
    asm volatile(
        "mma.sync.aligned.m16n8k16.row.col.f32.f16.f16.f32 "
        "{%0,%1,%2,%3}, {%4,%5,%6,%7}, {%8,%9}, {%0,%1,%2,%3};"
        : "+f"(d[0]), "+f"(d[1]), "+f"(d[2]), "+f"(d[3])
        : "r"(a[0]), "r"(a[1]), "r"(a[2]), "r"(a[3]), "r"(b0), "r"(b1));
}

// fp16 hi/lo split of an fp32 value (hi = rn(v), lo = rn(v - hi))
__device__ __forceinline__ void hsplit(float v, uint32_t& hi, uint32_t& lo) {
    __half h = __float2half_rn(v);
    float r = v - __half2float(h);
    __half l = __float2half_rn(r);
    hi = (uint32_t)(*reinterpret_cast<unsigned short*>(&h));
    lo = (uint32_t)(*reinterpret_cast<unsigned short*>(&l));
}
__device__ __forceinline__ uint32_t h1(float v) {
    __half h = __float2half_rn(v);
    return (uint32_t)(*reinterpret_cast<unsigned short*>(&h));
}

// ================= Kernel 1: HMMA fp16 2-split projection GEMM =============
// pre[m][g*128+n] = h( bias_g[n] + sum_k X[m][k] * W_g[k][n] )
// grid = 1024 m-tiles of 128; block 512 (16 warps: 4m x 4n).
// A split hi/lo fp16; B single fp16 copy per gate (all 5 resident).
#define A_STR 72   // padded row stride (elements) -> 144 B, conflict-free ldsm
#define B_STR 72

#define SM_AH 0
#define SM_AL 18432
#define SM_B  36864                       // + g*18432
#define SM_TOTAL (36864 + 5 * 18432)      // 129024

__global__ void __launch_bounds__(512, 1) gemm_pre_hmma(
    const float* __restrict__ X,
    const float* __restrict__ wf, const float* __restrict__ wi,
    const float* __restrict__ wo, const float* __restrict__ wc,
    const float* __restrict__ biasf, const float* __restrict__ biasi,
    const float* __restrict__ biaso, const float* __restrict__ biasc)
{
    extern __shared__ __align__(1024) char sm[];
    const uint32_t sbase = smem_u32(sm);
    const int tid  = threadIdx.x;
    const int lane = tid & 31;
    const int w    = tid >> 5;
    const int wm   = w >> 2;      // 0..3  (m quadrant, 32 rows)
    const int wn   = w & 3;       // 0..3  (n quarter, 32 cols)
    const int mb   = blockIdx.x * 128;

    // ---- load + split X tile: 128 rows x 64 fp32 -> A_hi / A_lo fp16 ----
    {
        const float4* X4 = (const float4*)(X + (size_t)mb * II);
#pragma unroll
        for (int it = 0; it < 4; it++) {
            int j = tid + it * 512;          // 2048 float4 total
            float4 v = X4[j];
            int row = j >> 4;
            int kq  = (j & 15) * 4;
            uint32_t h0, l0, h1v, l1, h2, l2, h3, l3;
            hsplit(v.x, h0, l0); hsplit(v.y, h1v, l1);
            hsplit(v.z, h2, l2); hsplit(v.w, h3, l3);
            uint32_t off = (uint32_t)(row * (A_STR * 2) + kq * 2);
            *(uint2*)(sm + SM_AH + off) = make_uint2(h0 | (h1v << 16), h2 | (h3 << 16));
            *(uint2*)(sm + SM_AL + off) = make_uint2(l0 | (l1 << 16), l2 | (l3 << 16));
        }
    }

    // ---- load + convert + transpose ALL gate weights -> Bsm[g][n][k] fp16 ----
    {
        const int n  = tid & 127;
        const int qu = tid >> 7;             // k quarter: 0..3
#pragma unroll 1
        for (int g = 0; g < 5; g++) {
            const float* W;
            if (g == 0)      W = wf;
            else if (g == 1) W = wf + II * OO;
            else if (g == 2) W = wi;
            else if (g == 3) W = wo;
            else             W = wc;
            char* bh = sm + SM_B + g * 18432;
#pragma unroll
            for (int i = 0; i < 8; i++) {
                int k0 = qu * 16 + 2 * i;
                float w0 = __ldg(W + (size_t)k0 * OO + n);
                float w1 = __ldg(W + (size_t)(k0 + 1) * OO + n);
                uint32_t off = (uint32_t)(n * (B_STR * 2) + k0 * 2);
                *(uint32_t*)(bh + off) = h1(w0) | (h1(w1) << 16);
            }
        }
    }
    __syncthreads();   // the ONLY block barrier

    // ldmatrix lane addresses (row = lane&15, col-half = lane>>4)
    const int lrow  = lane & 15;
    const int lcolb = (lane >> 4) * 16;     // byte offset of k-half
    uint32_t aAddrH[2], aAddrL[2];
#pragma unroll
    for (int mi = 0; mi < 2; mi++) {
        uint32_t ro = (uint32_t)((wm * 32 + mi * 16 + lrow) * (A_STR * 2) + lcolb);
        aAddrH[mi] = sbase + SM_AH + ro;
        aAddrL[mi] = sbase + SM_AL + ro;
    }
    uint32_t bAddr[2];
#pragma unroll
    for (int p = 0; p < 2; p++) {
        uint32_t ro = (uint32_t)((wn * 32 + p * 16 + lrow) * (B_STR * 2) + lcolb);
        bAddr[p] = sbase + SM_B + ro;
    }

    // A fragments hoisted: reused across all 5 gates
    uint32_t aH[4][2][4], aL[4][2][4];
#pragma unroll
    for (int ks = 0; ks < 4; ks++) {
        const uint32_t kb = (uint32_t)(ks * 32);
#pragma unroll
        for (int mi = 0; mi < 2; mi++) {
            ldsm_x4(aH[ks][mi][0], aH[ks][mi][1], aH[ks][mi][2], aH[ks][mi][3],
                    aAddrH[mi] + kb);
            ldsm_x4(aL[ks][mi][0], aL[ks][mi][1], aL[ks][mi][2], aL[ks][mi][3],
                    aAddrL[mi] + kb);
        }
    }

#pragma unroll 1
    for (int g = 0; g < 5; g++) {
        const float* bias;
        if (g == 0)      bias = biasf;
        else if (g == 1) bias = biasf + OO;
        else if (g == 2) bias = biasi;
        else if (g == 3) bias = biaso;
        else             bias = biasc;
        const uint32_t goff = (uint32_t)(g * 18432);

        float acc[2][4][4];
#pragma unroll
        for (int mi = 0; mi < 2; mi++)
#pragma unroll
            for (int ni = 0; ni < 4; ni++)
#pragma unroll
                for (int e = 0; e < 4; e++) acc[mi][ni][e] = 0.f;

#pragma unroll
        for (int ks = 0; ks < 4; ks++) {
            const uint32_t kb = (uint32_t)(ks * 32);
#pragma unroll
            for (int p = 0; p < 2; p++) {
                uint32_t b0, b1, b2, b3;
                ldsm_x4(b0, b1, b2, b3, bAddr[p] + goff + kb);
#pragma unroll
                for (int mi = 0; mi < 2; mi++) {
                    mma_f16(acc[mi][2 * p],     aH[ks][mi], b0, b2);
                    mma_f16(acc[mi][2 * p + 1], aH[ks][mi], b1, b3);
                    mma_f16(acc[mi][2 * p],     aL[ks][mi], b0, b2);
                    mma_f16(acc[mi][2 * p + 1], aL[ks][mi], b1, b3);
                }
            }
        }

        // ---- epilogue: bias + convert to fp16 + store (half2) ----
        {
            const int qr = lane >> 2;          // 0..7 row within 8
            const int qc = (lane & 3) * 2;     // col pair within 8
#pragma unroll
            for (int ni = 0; ni < 4; ni++) {
                int col = wn * 32 + ni * 8 + qc;
                float b0 = __ldg(bias + col);
                float b1 = __ldg(bias + col + 1);
#pragma unroll
                for (int mi = 0; mi < 2; mi++) {
                    int row = mb + wm * 32 + mi * 16 + qr;
                    size_t idx = (size_t)row * NPRE + (size_t)g * 128 + col;
                    __half2 v0 = __floats2half2_rn(acc[mi][ni][0] + b0,
                                                   acc[mi][ni][1] + b1);
                    __half2 v1 = __floats2half2_rn(acc[mi][ni][2] + b0,
                                                   acc[mi][ni][3] + b1);
                    *(__half2*)(g_preh + idx) = v0;
                    *(__half2*)(g_preh + idx + 8 * NPRE) = v1;
                }
            }
        }
    }
}

// ================= Kernel 2: wavefront recurrence (p2p warp pipeline) ======
__device__ __forceinline__ float sigf(float x) {
    float t;
    asm("tanh.approx.f32 %0, %1;" : "=f"(t) : "f"(0.5f * x));
    return fmaf(0.5f, t, 0.5f);
}
__device__ __forceinline__ float tanhapx(float x) {
    float y;
    asm("tanh.approx.f32 %0, %1;" : "=f"(y) : "f"(x));
    return y;
}

struct UC {
    float uf00, uf01, uf10, uf11;
    float ui0, ui1, uo0, uo1, uc0, uc1;
};

__device__ __forceinline__ void cell_compute(const float q[5], const UC& u,
                                             float hup, float hl,
                                             float sup, float sl,
                                             float& s, float& h)
{
    float pf0 = fmaf(u.uf01, hl, fmaf(u.uf00, hup, q[0]));
    float pf1 = fmaf(u.uf11, hl, fmaf(u.uf10, hup, q[1]));
    float pi  = fmaf(u.ui1,  hl, fmaf(u.ui0,  hup, q[2]));
    float po  = fmaf(u.uo1,  hl, fmaf(u.uo0,  hup, q[3]));
    float pc  = fmaf(u.uc1,  hl, fmaf(u.uc0,  hup, q[4]));
    float f0 = sigf(pf0);
    float f1 = sigf(pf1);
    float ig = sigf(pi);
    float og = sigf(po);
    float cg = sigf(pc);
    s = fmaf(f0, sup, fmaf(f1, sl, ig * cg));
    h = og * tanhapx(s);
}

// block = (b, o-group of 32). 32 warps; warp w owns rows 2w, 2w+1; lane = o.
__global__ void __launch_bounds__(1024, 1) mdlstm_rec_kernel(
    const float* __restrict__ uf, const float* __restrict__ ui,
    const float* __restrict__ uo, const float* __restrict__ uc,
    float* __restrict__ out)
{
    __shared__ float sh_s[4][32][32];   // [slot][producer warp][lane]
    __shared__ float sh_h[4][32][32];
    __shared__ int   ready[32];

    const int lane = threadIdx.x & 31;
    const int w    = threadIdx.x >> 5;
    const int b    = blockIdx.x >> 2;
    const int og   = blockIdx.x & 3;
    const int o    = og * 32 + lane;

    if (threadIdx.x < 32) ready[threadIdx.x] = -1;
    __syncthreads();
    const uint32_t raddr = smem_u32(ready);
    const uint32_t r_prev = raddr + 4u * (uint32_t)(w - 1);
    const uint32_t r_next = raddr + 4u * (uint32_t)(w + 1);
    const uint32_t r_self = raddr + 4u * (uint32_t)w;

    UC u;
    u.uf00 = uf[o];        u.uf01 = uf[128 + o];
    u.uf10 = uf[256 + o];  u.uf11 = uf[384 + o];
    u.ui0  = ui[o];        u.ui1  = ui[128 + o];
    u.uo0  = uo[o];        u.uo1  = uo[128 + o];
    u.uc0  = uc[o];        u.uc1  = uc[128 + o];

    const __half* preb = g_preh + (size_t)b * NPRE + o;  // + cell*20480
    float* ob = out + b * 128 + o;                       // + cell*4096

    const int r0base = (2 * w) * 64;   // row 2w, col 0 (cell index)
    const int r1base = r0base + 64;    // row 2w+1

    const __half* pf0 = preb + (size_t)r0base * 20480;
    const __half* pf1 = preb + (size_t)r1base * 20480;
    float* ob0 = ob + (size_t)r0base * 4096;
    float* ob1 = ob + (size_t)r1base * 4096;

    float q0[5], q1[5];
#pragma unroll
    for (int z = 0; z < 5; z++) q0[z] = __half2float(__ldg(pf0 + z * 128));
    pf0 += 20480;

    float s0l = 0.f, h0l = 0.f;
    float s1l = 0.f, h1l = 0.f;

    const int t0 = 2 * w;

#pragma unroll 1
    for (int step = 0; step <= 64; step++) {
        const int t  = t0 + step;
        const int c0 = step;       // row0 column this step (valid if <=63)

        // ---- prefetch next pre-activations ----
        float n0[5], n1[5];
        if (step <= 62) {
#pragma unroll
            for (int z = 0; z < 5; z++) n0[z] = __half2float(__ldg(pf0 + z * 128));
            pf0 += 20480;
        }
        if (step <= 63) {
#pragma unroll
            for (int z = 0; z < 5; z++) n1[z] = __half2float(__ldg(pf1 + z * 128));
            pf1 += 20480;
        }

        const float s0_prev = s0l, h0_prev = h0l;

        // ---- row 0 (consumes warp w-1's step t-1 publish) ----
        if (c0 <= 63) {
            float sup, hup;
            if (w == 0) {
                sup = 0.f; hup = 0.f;
            } else {
                const int need = t - 1;
                int v;
                do {
                    asm volatile("ld.acquire.cta.shared.b32 %0, [%1];"
                                 : "=r"(v) : "r"(r_prev) : "memory");
                } while (v < need);
                const int ps = need & 3;
                sup = sh_s[ps][w - 1][lane];
                hup = sh_h[ps][w - 1][lane];
            }
            float s, h;
            cell_compute(q0, u, hup, h0l, sup, s0l, s, h);
            *ob0 = s; ob0 += 4096;
            s0l = s; h0l = h;
        }

        // ---- row 1 (publishes for warp w+1) ----
        if (step >= 1) {
            float s, h;
            cell_compute(q1, u, h0_prev, h1l, s0_prev, s1l, s, h);
            *ob1 = s; ob1 += 4096;
            s1l = s; h1l = h;
            if (w < 31) {
                if (t >= t0 + 5) {
                    const int need = t - 3;
                    int v;
                    do {
                        asm volatile("ld.acquire.cta.shared.b32 %0, [%1];"
                                     : "=r"(v) : "r"(r_next) : "memory");
                    } while (v < need);
                }
                const int slot = t & 3;
                sh_s[slot][w][lane] = s;
                sh_h[slot][w][lane] = h;
            }
        }

        // ---- publish progress ----
        if (lane == 0) {
            asm volatile("st.release.cta.shared.b32 [%0], %1;"
                         :: "r"(r_self), "r"(t) : "memory");
        }

#pragma unroll
        for (int z = 0; z < 5; z++) { q0[z] = n0[z]; q1[z] = n1[z]; }
    }
}

// ================= launcher =================
extern "C" void kernel_launch(void* const* d_in, const int* in_sizes, int n_in,
                              void* d_out, int out_size) {
    (void)in_sizes; (void)n_in; (void)out_size;
    const float* x     = (const float*)d_in[0];
    const float* wf    = (const float*)d_in[1];
    const float* uf    = (const float*)d_in[2];
    const float* biasf = (const float*)d_in[3];
    const float* wi    = (const float*)d_in[4];
    const float* ui    = (const float*)d_in[5];
    const float* biasi = (const float*)d_in[6];
    const float* wo    = (const float*)d_in[7];
    const float* uo    = (const float*)d_in[8];
    const float* biaso = (const float*)d_in[9];
    const float* wc    = (const float*)d_in[10];
    const float* uc    = (const float*)d_in[11];
    const float* biasc = (const float*)d_in[12];
    float* out = (float*)d_out;

    cudaFuncSetAttribute(gemm_pre_hmma,
                         cudaFuncAttributeMaxDynamicSharedMemorySize, SM_TOTAL);
    gemm_pre_hmma<<<1024, 512, SM_TOTAL>>>(
        x, wf, wi, wo, wc, biasf, biasi, biaso, biasc);
    mdlstm_rec_kernel<<<128, 1024>>>(uf, ui, uo, uc, out);
}

// round 6
// speedup vs baseline: 1.0074x; 1.0074x over previous
#include <cuda_runtime.h>
#include <cuda_fp16.h>
#include <cstdint>
#include <cstddef>

// Problem dims
#define D1 64
#define D2 64
#define BB 32
#define II 64
#define OO 128
#define M_TOT (D1 * D2 * BB)   // 131072

// Packed pre-activations: [cell][word p=0..2][o=0..127] as uint32.
// word0 = (f0, f1) halves, word1 = (i, o), word2 = (c, pad). Bias folded in.
#define NPW 384                 // words per cell = 3*128
__device__ uint32_t g_pk[(size_t)M_TOT * NPW];

// ========================= helpers =========================
__device__ __forceinline__ uint32_t smem_u32(const void* p) {
    uint32_t a;
    asm("{ .reg .u64 t; cvta.to.shared.u64 t, %1; cvt.u32.u64 %0, t; }"
        : "=r"(a) : "l"(p));
    return a;
}

__device__ __forceinline__ void ldsm_x4(uint32_t& r0, uint32_t& r1,
                                        uint32_t& r2, uint32_t& r3,
                                        uint32_t addr) {
    asm volatile("ldmatrix.sync.aligned.m8n8.x4.shared.b16 {%0,%1,%2,%3}, [%4];"
                 : "=r"(r0), "=r"(r1), "=r"(r2), "=r"(r3) : "r"(addr));
}

// D += A * B  (m16n8k16, fp16 in, f32 accum)
__device__ __forceinline__ void mma_f16(float* d, const uint32_t* a,
                                        uint32_t b0, uint32_t b1) {
    asm volatile(
        "mma.sync.aligned.m16n8k16.row.col.f32.f16.f16.f32 "
        "{%0,%1,%2,%3}, {%4,%5,%6,%7}, {%8,%9}, {%0,%1,%2,%3};"
        : "+f"(d[0]), "+f"(d[1]), "+f"(d[2]), "+f"(d[3])
        : "r"(a[0]), "r"(a[1]), "r"(a[2]), "r"(a[3]), "r"(b0), "r"(b1));
}

// fp16 hi/lo split of an fp32 value
__device__ __forceinline__ void hsplit(float v, uint32_t& hi, uint32_t& lo) {
    __half h = __float2half_rn(v);
    float r = v - __half2float(h);
    __half l = __float2half_rn(r);
    hi = (uint32_t)(*reinterpret_cast<unsigned short*>(&h));
    lo = (uint32_t)(*reinterpret_cast<unsigned short*>(&l));
}
__device__ __forceinline__ uint32_t h1(float v) {
    __half h = __float2half_rn(v);
    return (uint32_t)(*reinterpret_cast<unsigned short*>(&h));
}
__device__ __forceinline__ uint32_t packh2(float a, float b) {
    __half2 h = __floats2half2_rn(a, b);   // low = a, high = b
    return *reinterpret_cast<uint32_t*>(&h);
}
__device__ __forceinline__ float2 up2(uint32_t w) {
    __half2 h = *reinterpret_cast<__half2*>(&w);
    return __half22float2(h);
}

// ================= Kernel 1: HMMA fp16 2-split projection GEMM =============
// Computes gates in pairs, writes packed uint32 words.
#define A_STR 72
#define B_STR 72

#define SM_AH 0
#define SM_AL 18432
#define SM_B  36864                       // + g*18432
#define SM_TOTAL (36864 + 5 * 18432)      // 129024

__global__ void __launch_bounds__(512, 1) gemm_pre_hmma(
    const float* __restrict__ X,
    const float* __restrict__ wf, const float* __restrict__ wi,
    const float* __restrict__ wo, const float* __restrict__ wc,
    const float* __restrict__ biasf, const float* __restrict__ biasi,
    const float* __restrict__ biaso, const float* __restrict__ biasc)
{
    extern __shared__ __align__(1024) char sm[];
    const uint32_t sbase = smem_u32(sm);
    const int tid  = threadIdx.x;
    const int lane = tid & 31;
    const int w    = tid >> 5;
    const int wm   = w >> 2;      // 0..3  (m quadrant, 32 rows)
    const int wn   = w & 3;       // 0..3  (n quarter, 32 cols)
    const int mb   = blockIdx.x * 128;

    // ---- load + split X tile: 128 rows x 64 fp32 -> A_hi / A_lo fp16 ----
    {
        const float4* X4 = (const float4*)(X + (size_t)mb * II);
#pragma unroll
        for (int it = 0; it < 4; it++) {
            int j = tid + it * 512;
            float4 v = X4[j];
            int row = j >> 4;
            int kq  = (j & 15) * 4;
            uint32_t h0, l0, h1v, l1, h2, l2, h3, l3;
            hsplit(v.x, h0, l0); hsplit(v.y, h1v, l1);
            hsplit(v.z, h2, l2); hsplit(v.w, h3, l3);
            uint32_t off = (uint32_t)(row * (A_STR * 2) + kq * 2);
            *(uint2*)(sm + SM_AH + off) = make_uint2(h0 | (h1v << 16), h2 | (h3 << 16));
            *(uint2*)(sm + SM_AL + off) = make_uint2(l0 | (l1 << 16), l2 | (l3 << 16));
        }
    }

    // ---- load + convert + transpose ALL gate weights -> Bsm[g][n][k] fp16 ----
    {
        const int n  = tid & 127;
        const int qu = tid >> 7;
#pragma unroll 1
        for (int g = 0; g < 5; g++) {
            const float* W;
            if (g == 0)      W = wf;
            else if (g == 1) W = wf + II * OO;
            else if (g == 2) W = wi;
            else if (g == 3) W = wo;
            else             W = wc;
            char* bh = sm + SM_B + g * 18432;
#pragma unroll
            for (int i = 0; i < 8; i++) {
                int k0 = qu * 16 + 2 * i;
                float w0 = __ldg(W + (size_t)k0 * OO + n);
                float w1 = __ldg(W + (size_t)(k0 + 1) * OO + n);
                uint32_t off = (uint32_t)(n * (B_STR * 2) + k0 * 2);
                *(uint32_t*)(bh + off) = h1(w0) | (h1(w1) << 16);
            }
        }
    }
    __syncthreads();

    const int lrow  = lane & 15;
    const int lcolb = (lane >> 4) * 16;
    uint32_t aAddrH[2], aAddrL[2];
#pragma unroll
    for (int mi = 0; mi < 2; mi++) {
        uint32_t ro = (uint32_t)((wm * 32 + mi * 16 + lrow) * (A_STR * 2) + lcolb);
        aAddrH[mi] = sbase + SM_AH + ro;
        aAddrL[mi] = sbase + SM_AL + ro;
    }
    uint32_t bAddr[2];
#pragma unroll
    for (int p = 0; p < 2; p++) {
        uint32_t ro = (uint32_t)((wn * 32 + p * 16 + lrow) * (B_STR * 2) + lcolb);
        bAddr[p] = sbase + SM_B + ro;
    }

    const int qr = lane >> 2;          // 0..7 row within 8
    const int qc = (lane & 3) * 2;     // col pair within 8

    // ---- gate pairs: (0,1), (2,3), (4,-) ----
#pragma unroll 1
    for (int pr = 0; pr < 3; pr++) {
        const int gA = 2 * pr;
        const bool hasB = (pr < 2);
        const float* biasA;
        const float* biasB = biasc;   // dummy default
        if (pr == 0)      { biasA = biasf;      biasB = biasf + OO; }
        else if (pr == 1) { biasA = biasi;      biasB = biaso;      }
        else              { biasA = biasc;                          }
        const uint32_t gAoff = (uint32_t)(gA * 18432);
        const uint32_t gBoff = gAoff + 18432;

        float accA[2][4][4], accB[2][4][4];
#pragma unroll
        for (int mi = 0; mi < 2; mi++)
#pragma unroll
            for (int ni = 0; ni < 4; ni++)
#pragma unroll
                for (int e = 0; e < 4; e++) { accA[mi][ni][e] = 0.f; accB[mi][ni][e] = 0.f; }

#pragma unroll
        for (int ks = 0; ks < 4; ks++) {
            const uint32_t kb = (uint32_t)(ks * 32);
            uint32_t aH[2][4], aL[2][4];
#pragma unroll
            for (int mi = 0; mi < 2; mi++) {
                ldsm_x4(aH[mi][0], aH[mi][1], aH[mi][2], aH[mi][3], aAddrH[mi] + kb);
                ldsm_x4(aL[mi][0], aL[mi][1], aL[mi][2], aL[mi][3], aAddrL[mi] + kb);
            }
#pragma unroll
            for (int pq = 0; pq < 2; pq++) {
                uint32_t b0, b1, b2, b3;
                ldsm_x4(b0, b1, b2, b3, bAddr[pq] + gAoff + kb);
#pragma unroll
                for (int mi = 0; mi < 2; mi++) {
                    mma_f16(accA[mi][2 * pq],     aH[mi], b0, b2);
                    mma_f16(accA[mi][2 * pq + 1], aH[mi], b1, b3);
                    mma_f16(accA[mi][2 * pq],     aL[mi], b0, b2);
                    mma_f16(accA[mi][2 * pq + 1], aL[mi], b1, b3);
                }
                if (hasB) {
                    uint32_t c0, c1, c2, c3;
                    ldsm_x4(c0, c1, c2, c3, bAddr[pq] + gBoff + kb);
#pragma unroll
                    for (int mi = 0; mi < 2; mi++) {
                        mma_f16(accB[mi][2 * pq],     aH[mi], c0, c2);
                        mma_f16(accB[mi][2 * pq + 1], aH[mi], c1, c3);
                        mma_f16(accB[mi][2 * pq],     aL[mi], c0, c2);
                        mma_f16(accB[mi][2 * pq + 1], aL[mi], c1, c3);
                    }
                }
            }
        }

        // ---- epilogue: pack two gates into one uint32 word, uint2 stores ----
#pragma unroll
        for (int ni = 0; ni < 4; ni++) {
            int col = wn * 32 + ni * 8 + qc;
            float bA0 = __ldg(biasA + col);
            float bA1 = __ldg(biasA + col + 1);
            float bB0 = hasB ? __ldg(biasB + col)     : 0.f;
            float bB1 = hasB ? __ldg(biasB + col + 1) : 0.f;
#pragma unroll
            for (int mi = 0; mi < 2; mi++) {
                int row = mb + wm * 32 + mi * 16 + qr;
                size_t idx = (size_t)row * NPW + (size_t)pr * 128 + col;
                uint32_t w0, w1, w2, w3;
                if (hasB) {
                    w0 = packh2(accA[mi][ni][0] + bA0, accB[mi][ni][0] + bB0);
                    w1 = packh2(accA[mi][ni][1] + bA1, accB[mi][ni][1] + bB1);
                    w2 = packh2(accA[mi][ni][2] + bA0, accB[mi][ni][2] + bB0);
                    w3 = packh2(accA[mi][ni][3] + bA1, accB[mi][ni][3] + bB1);
                } else {
                    w0 = h1(accA[mi][ni][0] + bA0);
                    w1 = h1(accA[mi][ni][1] + bA1);
                    w2 = h1(accA[mi][ni][2] + bA0);
                    w3 = h1(accA[mi][ni][3] + bA1);
                }
                *(uint2*)(g_pk + idx) = make_uint2(w0, w1);
                *(uint2*)(g_pk + idx + (size_t)8 * NPW) = make_uint2(w2, w3);
            }
        }
    }
}

// ================= Kernel 2: wavefront recurrence (p2p warp pipeline) ======
__device__ __forceinline__ float sigf(float x) {
    float t;
    asm("tanh.approx.f32 %0, %1;" : "=f"(t) : "f"(0.5f * x));
    return fmaf(0.5f, t, 0.5f);
}
__device__ __forceinline__ float tanhapx(float x) {
    float y;
    asm("tanh.approx.f32 %0, %1;" : "=f"(y) : "f"(x));
    return y;
}

struct UC {
    float uf00, uf01, uf10, uf11;
    float ui0, ui1, uo0, uo1, uc0, uc1;
};

__device__ __forceinline__ void cell_compute(const float q[5], const UC& u,
                                             float hup, float hl,
                                             float sup, float sl,
                                             float& s, float& h)
{
    float pf0 = fmaf(u.uf01, hl, fmaf(u.uf00, hup, q[0]));
    float pf1 = fmaf(u.uf11, hl, fmaf(u.uf10, hup, q[1]));
    float pi  = fmaf(u.ui1,  hl, fmaf(u.ui0,  hup, q[2]));
    float po  = fmaf(u.uo1,  hl, fmaf(u.uo0,  hup, q[3]));
    float pc  = fmaf(u.uc1,  hl, fmaf(u.uc0,  hup, q[4]));
    float f0 = sigf(pf0);
    float f1 = sigf(pf1);
    float ig = sigf(pi);
    float og = sigf(po);
    float cg = sigf(pc);
    s = fmaf(f0, sup, fmaf(f1, sl, ig * cg));
    h = og * tanhapx(s);
}

// block = (b, o-group of 32). 32 warps; warp w owns rows 2w, 2w+1; lane = o.
// Per-cell stride in g_pk (for fixed b, advancing one column) = 32*NPW words.
#define CSTRIDE (32 * NPW)   // 12288

__global__ void __launch_bounds__(1024, 1) mdlstm_rec_kernel(
    const float* __restrict__ uf, const float* __restrict__ ui,
    const float* __restrict__ uo, const float* __restrict__ uc,
    float* __restrict__ out)
{
    __shared__ float sh_s[4][32][32];
    __shared__ float sh_h[4][32][32];
    __shared__ int   ready[32];

    const int lane = threadIdx.x & 31;
    const int w    = threadIdx.x >> 5;
    const int b    = blockIdx.x >> 2;
    const int og   = blockIdx.x & 3;
    const int o    = og * 32 + lane;

    if (threadIdx.x < 32) ready[threadIdx.x] = -1;
    __syncthreads();
    const uint32_t raddr = smem_u32(ready);
    const uint32_t r_prev = raddr + 4u * (uint32_t)(w - 1);
    const uint32_t r_next = raddr + 4u * (uint32_t)(w + 1);
    const uint32_t r_self = raddr + 4u * (uint32_t)w;

    UC u;
    u.uf00 = uf[o];        u.uf01 = uf[128 + o];
    u.uf10 = uf[256 + o];  u.uf11 = uf[384 + o];
    u.ui0  = ui[o];        u.ui1  = ui[128 + o];
    u.uo0  = uo[o];        u.uo1  = uo[128 + o];
    u.uc0  = uc[o];        u.uc1  = uc[128 + o];

    const uint32_t* preb = g_pk + (size_t)b * NPW + o;
    float* ob = out + b * 128 + o;

    const int r0base = (2 * w) * 64;
    const int r1base = r0base + 64;

    const uint32_t* pf0 = preb + (size_t)r0base * CSTRIDE;
    const uint32_t* pf1 = preb + (size_t)r1base * CSTRIDE;
    float* ob0 = ob + (size_t)r0base * 4096;
    float* ob1 = ob + (size_t)r1base * 4096;

    float q0[5], q1[5];
    {
        uint32_t w0 = __ldg(pf0), w1 = __ldg(pf0 + 128), w2 = __ldg(pf0 + 256);
        float2 a = up2(w0), bb = up2(w1), cc = up2(w2);
        q0[0] = a.x; q0[1] = a.y; q0[2] = bb.x; q0[3] = bb.y; q0[4] = cc.x;
        pf0 += CSTRIDE;
    }

    float s0l = 0.f, h0l = 0.f;
    float s1l = 0.f, h1l = 0.f;

    const int t0 = 2 * w;

#pragma unroll 1
    for (int step = 0; step <= 64; step++) {
        const int t  = t0 + step;
        const int c0 = step;

        // ---- prefetch next pre-activations (full-width LDG.32) ----
        float n0[5], n1[5];
        if (step <= 62) {
            uint32_t w0 = __ldg(pf0), w1 = __ldg(pf0 + 128), w2 = __ldg(pf0 + 256);
            float2 a = up2(w0), bb = up2(w1), cc = up2(w2);
            n0[0] = a.x; n0[1] = a.y; n0[2] = bb.x; n0[3] = bb.y; n0[4] = cc.x;
            pf0 += CSTRIDE;
        }
        if (step <= 63) {
            uint32_t w0 = __ldg(pf1), w1 = __ldg(pf1 + 128), w2 = __ldg(pf1 + 256);
            float2 a = up2(w0), bb = up2(w1), cc = up2(w2);
            n1[0] = a.x; n1[1] = a.y; n1[2] = bb.x; n1[3] = bb.y; n1[4] = cc.x;
            pf1 += CSTRIDE;
        }

        const float s0_prev = s0l, h0_prev = h0l;

        // ---- row 0 (consumes warp w-1's step t-1 publish) ----
        if (c0 <= 63) {
            float sup, hup;
            if (w == 0) {
                sup = 0.f; hup = 0.f;
            } else {
                const int need = t - 1;
                int v;
                do {
                    asm volatile("ld.acquire.cta.shared.b32 %0, [%1];"
                                 : "=r"(v) : "r"(r_prev) : "memory");
                } while (v < need);
                const int ps = need & 3;
                sup = sh_s[ps][w - 1][lane];
                hup = sh_h[ps][w - 1][lane];
            }
            float s, h;
            cell_compute(q0, u, hup, h0l, sup, s0l, s, h);
            *ob0 = s; ob0 += 4096;
            s0l = s; h0l = h;
        }

        // ---- row 1 (publishes for warp w+1) ----
        if (step >= 1) {
            float s, h;
            cell_compute(q1, u, h0_prev, h1l, s0_prev, s1l, s, h);
            *ob1 = s; ob1 += 4096;
            s1l = s; h1l = h;
            if (w < 31) {
                if (t >= t0 + 5) {
                    const int need = t - 3;
                    int v;
                    do {
                        asm volatile("ld.acquire.cta.shared.b32 %0, [%1];"
                                     : "=r"(v) : "r"(r_next) : "memory");
                    } while (v < need);
                }
                const int slot = t & 3;
                sh_s[slot][w][lane] = s;
                sh_h[slot][w][lane] = h;
            }
        }

        // ---- publish progress ----
        if (lane == 0) {
            asm volatile("st.release.cta.shared.b32 [%0], %1;"
                         :: "r"(r_self), "r"(t) : "memory");
        }

#pragma unroll
        for (int z = 0; z < 5; z++) { q0[z] = n0[z]; q1[z] = n1[z]; }
    }
}

// ================= launcher =================
extern "C" void kernel_launch(void* const* d_in, const int* in_sizes, int n_in,
                              void* d_out, int out_size) {
    (void)in_sizes; (void)n_in; (void)out_size;
    const float* x     = (const float*)d_in[0];
    const float* wf    = (const float*)d_in[1];
    const float* uf    = (const float*)d_in[2];
    const float* biasf = (const float*)d_in[3];
    const float* wi    = (const float*)d_in[4];
    const float* ui    = (const float*)d_in[5];
    const float* biasi = (const float*)d_in[6];
    const float* wo    = (const float*)d_in[7];
    const float* uo    = (const float*)d_in[8];
    const float* biaso = (const float*)d_in[9];
    const float* wc    = (const float*)d_in[10];
    const float* uc    = (const float*)d_in[11];
    const float* biasc = (const float*)d_in[12];
    float* out = (float*)d_out;

    cudaFuncSetAttribute(gemm_pre_hmma,
                         cudaFuncAttributeMaxDynamicSharedMemorySize, SM_TOTAL);
    gemm_pre_hmma<<<1024, 512, SM_TOTAL>>>(
        x, wf, wi, wo, wc, biasf, biasi, biaso, biasc);
    mdlstm_rec_kernel<<<128, 1024>>>(uf, ui, uo, uc, out);
}

// round 7
// speedup vs baseline: 1.5632x; 1.5516x over previous
#include <cuda_runtime.h>
#include <cuda_fp16.h>
#include <cstdint>
#include <cstddef>

// Problem dims
#define D1 64
#define D2 64
#define BB 32
#define II 64
#define OO 128
#define M_TOT (D1 * D2 * BB)   // 131072

// Packed pre-activations: [cell][word p=0..2][o=0..127] as uint32.
// word0 = (f0, f1) halves, word1 = (i, o), word2 = (c, pad). Bias folded in.
#define NPW 384                 // words per cell = 3*128
#define CSTRIDE (32 * NPW)      // advance one column (fixed b) = 12288 words
__device__ uint32_t g_pk[(size_t)M_TOT * NPW];

// ========================= helpers =========================
__device__ __forceinline__ uint32_t smem_u32(const void* p) {
    uint32_t a;
    asm("{ .reg .u64 t; cvta.to.shared.u64 t, %1; cvt.u32.u64 %0, t; }"
        : "=r"(a) : "l"(p));
    return a;
}

__device__ __forceinline__ void ldsm_x4(uint32_t& r0, uint32_t& r1,
                                        uint32_t& r2, uint32_t& r3,
                                        uint32_t addr) {
    asm volatile("ldmatrix.sync.aligned.m8n8.x4.shared.b16 {%0,%1,%2,%3}, [%4];"
                 : "=r"(r0), "=r"(r1), "=r"(r2), "=r"(r3) : "r"(addr));
}

__device__ __forceinline__ void mma_f16(float* d, const uint32_t* a,
                                        uint32_t b0, uint32_t b1) {
    asm volatile(
        "mma.sync.aligned.m16n8k16.row.col.f32.f16.f16.f32 "
        "{%0,%1,%2,%3}, {%4,%5,%6,%7}, {%8,%9}, {%0,%1,%2,%3};"
        : "+f"(d[0]), "+f"(d[1]), "+f"(d[2]), "+f"(d[3])
        : "r"(a[0]), "r"(a[1]), "r"(a[2]), "r"(a[3]), "r"(b0), "r"(b1));
}

__device__ __forceinline__ uint32_t h1(float v) {
    __half h = __float2half_rn(v);
    return (uint32_t)(*reinterpret_cast<unsigned short*>(&h));
}
__device__ __forceinline__ uint32_t packh2(float a, float b) {
    __half2 h = __floats2half2_rn(a, b);
    return *reinterpret_cast<uint32_t*>(&h);
}
__device__ __forceinline__ float2 up2(uint32_t w) {
    __half2 h = *reinterpret_cast<__half2*>(&w);
    return __half22float2(h);
}

// ================= Kernel 1: HMMA fp16 (single-precision A) GEMM ===========
#define A_STR 72
#define B_STR 72

#define SM_A  0
#define SM_B  18432                       // + g*18432
#define SM_TOTAL (18432 * 6)              // 110592

__global__ void __launch_bounds__(512, 1) gemm_pre_hmma(
    const float* __restrict__ X,
    const float* __restrict__ wf, const float* __restrict__ wi,
    const float* __restrict__ wo, const float* __restrict__ wc,
    const float* __restrict__ biasf, const float* __restrict__ biasi,
    const float* __restrict__ biaso, const float* __restrict__ biasc)
{
    extern __shared__ __align__(1024) char sm[];
    const uint32_t sbase = smem_u32(sm);
    const int tid  = threadIdx.x;
    const int lane = tid & 31;
    const int w    = tid >> 5;
    const int wm   = w >> 2;
    const int wn   = w & 3;
    const int mb   = blockIdx.x * 128;

    // ---- load + convert X tile: 128 rows x 64 fp32 -> fp16 ----
    {
        const float4* X4 = (const float4*)(X + (size_t)mb * II);
#pragma unroll
        for (int it = 0; it < 4; it++) {
            int j = tid + it * 512;
            float4 v = X4[j];
            int row = j >> 4;
            int kq  = (j & 15) * 4;
            uint32_t off = (uint32_t)(row * (A_STR * 2) + kq * 2);
            *(uint2*)(sm + SM_A + off) =
                make_uint2(h1(v.x) | (h1(v.y) << 16), h1(v.z) | (h1(v.w) << 16));
        }
    }

    // ---- load + convert + transpose ALL gate weights -> Bsm[g][n][k] ----
    {
        const int n  = tid & 127;
        const int qu = tid >> 7;
#pragma unroll 1
        for (int g = 0; g < 5; g++) {
            const float* W;
            if (g == 0)      W = wf;
            else if (g == 1) W = wf + II * OO;
            else if (g == 2) W = wi;
            else if (g == 3) W = wo;
            else             W = wc;
            char* bh = sm + SM_B + g * 18432;
#pragma unroll
            for (int i = 0; i < 8; i++) {
                int k0 = qu * 16 + 2 * i;
                float w0 = __ldg(W + (size_t)k0 * OO + n);
                float w1 = __ldg(W + (size_t)(k0 + 1) * OO + n);
                uint32_t off = (uint32_t)(n * (B_STR * 2) + k0 * 2);
                *(uint32_t*)(bh + off) = h1(w0) | (h1(w1) << 16);
            }
        }
    }
    __syncthreads();

    const int lrow  = lane & 15;
    const int lcolb = (lane >> 4) * 16;
    uint32_t aAddr[2];
#pragma unroll
    for (int mi = 0; mi < 2; mi++) {
        uint32_t ro = (uint32_t)((wm * 32 + mi * 16 + lrow) * (A_STR * 2) + lcolb);
        aAddr[mi] = sbase + SM_A + ro;
    }
    uint32_t bAddr[2];
#pragma unroll
    for (int p = 0; p < 2; p++) {
        uint32_t ro = (uint32_t)((wn * 32 + p * 16 + lrow) * (B_STR * 2) + lcolb);
        bAddr[p] = sbase + SM_B + ro;
    }

    // A fragments hoisted (reused across gates)
    uint32_t aF[4][2][4];
#pragma unroll
    for (int ks = 0; ks < 4; ks++) {
        const uint32_t kb = (uint32_t)(ks * 32);
#pragma unroll
        for (int mi = 0; mi < 2; mi++)
            ldsm_x4(aF[ks][mi][0], aF[ks][mi][1], aF[ks][mi][2], aF[ks][mi][3],
                    aAddr[mi] + kb);
    }

    const int qr = lane >> 2;
    const int qc = (lane & 3) * 2;

    // ---- gate pairs: (0,1), (2,3), (4,-) ----
#pragma unroll 1
    for (int pr = 0; pr < 3; pr++) {
        const int gA = 2 * pr;
        const bool hasB = (pr < 2);
        const float* biasA;
        const float* biasB = biasc;
        if (pr == 0)      { biasA = biasf; biasB = biasf + OO; }
        else if (pr == 1) { biasA = biasi; biasB = biaso;      }
        else              { biasA = biasc;                     }
        const uint32_t gAoff = (uint32_t)(gA * 18432);
        const uint32_t gBoff = gAoff + 18432;

        float accA[2][4][4], accB[2][4][4];
#pragma unroll
        for (int mi = 0; mi < 2; mi++)
#pragma unroll
            for (int ni = 0; ni < 4; ni++)
#pragma unroll
                for (int e = 0; e < 4; e++) { accA[mi][ni][e] = 0.f; accB[mi][ni][e] = 0.f; }

#pragma unroll
        for (int ks = 0; ks < 4; ks++) {
            const uint32_t kb = (uint32_t)(ks * 32);
#pragma unroll
            for (int pq = 0; pq < 2; pq++) {
                uint32_t b0, b1, b2, b3;
                ldsm_x4(b0, b1, b2, b3, bAddr[pq] + gAoff + kb);
#pragma unroll
                for (int mi = 0; mi < 2; mi++) {
                    mma_f16(accA[mi][2 * pq],     aF[ks][mi], b0, b2);
                    mma_f16(accA[mi][2 * pq + 1], aF[ks][mi], b1, b3);
                }
                if (hasB) {
                    uint32_t c0, c1, c2, c3;
                    ldsm_x4(c0, c1, c2, c3, bAddr[pq] + gBoff + kb);
#pragma unroll
                    for (int mi = 0; mi < 2; mi++) {
                        mma_f16(accB[mi][2 * pq],     aF[ks][mi], c0, c2);
                        mma_f16(accB[mi][2 * pq + 1], aF[ks][mi], c1, c3);
                    }
                }
            }
        }

        // ---- epilogue: pack two gates into one uint32 word, uint2 stores ----
#pragma unroll
        for (int ni = 0; ni < 4; ni++) {
            int col = wn * 32 + ni * 8 + qc;
            float bA0 = __ldg(biasA + col);
            float bA1 = __ldg(biasA + col + 1);
            float bB0 = hasB ? __ldg(biasB + col)     : 0.f;
            float bB1 = hasB ? __ldg(biasB + col + 1) : 0.f;
#pragma unroll
            for (int mi = 0; mi < 2; mi++) {
                int row = mb + wm * 32 + mi * 16 + qr;
                size_t idx = (size_t)row * NPW + (size_t)pr * 128 + col;
                uint32_t w0, w1, w2, w3;
                if (hasB) {
                    w0 = packh2(accA[mi][ni][0] + bA0, accB[mi][ni][0] + bB0);
                    w1 = packh2(accA[mi][ni][1] + bA1, accB[mi][ni][1] + bB1);
                    w2 = packh2(accA[mi][ni][2] + bA0, accB[mi][ni][2] + bB0);
                    w3 = packh2(accA[mi][ni][3] + bA1, accB[mi][ni][3] + bB1);
                } else {
                    w0 = h1(accA[mi][ni][0] + bA0);
                    w1 = h1(accA[mi][ni][1] + bA1);
                    w2 = h1(accA[mi][ni][2] + bA0);
                    w3 = h1(accA[mi][ni][3] + bA1);
                }
                *(uint2*)(g_pk + idx) = make_uint2(w0, w1);
                *(uint2*)(g_pk + idx + (size_t)8 * NPW) = make_uint2(w2, w3);
            }
        }
    }
}

// ================= Kernel 2: wavefront recurrence, 4 rows/warp, deep PF ====
__device__ __forceinline__ float sigf(float x) {
    float t;
    asm("tanh.approx.f32 %0, %1;" : "=f"(t) : "f"(0.5f * x));
    return fmaf(0.5f, t, 0.5f);
}
__device__ __forceinline__ float tanhapx(float x) {
    float y;
    asm("tanh.approx.f32 %0, %1;" : "=f"(y) : "f"(x));
    return y;
}

struct UC {
    float uf00, uf01, uf10, uf11;
    float ui0, ui1, uo0, uo1, uc0, uc1;
};

__device__ __forceinline__ void cell_w(const uint32_t qw[3], const UC& u,
                                       float hup, float hl,
                                       float sup, float sl,
                                       float& s, float& h)
{
    float2 qa = up2(qw[0]);   // (f0, f1)
    float2 qb = up2(qw[1]);   // (i, o)
    float2 qcv = up2(qw[2]);  // (c, pad)
    float pf0 = fmaf(u.uf01, hl, fmaf(u.uf00, hup, qa.x));
    float pf1 = fmaf(u.uf11, hl, fmaf(u.uf10, hup, qa.y));
    float pi  = fmaf(u.ui1,  hl, fmaf(u.ui0,  hup, qb.x));
    float po  = fmaf(u.uo1,  hl, fmaf(u.uo0,  hup, qb.y));
    float pc  = fmaf(u.uc1,  hl, fmaf(u.uc0,  hup, qcv.x));
    float f0 = sigf(pf0);
    float f1 = sigf(pf1);
    float ig = sigf(pi);
    float og = sigf(po);
    float cg = sigf(pc);
    s = fmaf(f0, sup, fmaf(f1, sl, ig * cg));
    h = og * tanhapx(s);
}

// block = (b, o-group of 32). 16 warps; warp w owns rows 4w..4w+3; lane = o.
// All warps share loop counter s (0..67); lag enforced by ready[] waits.
// Prefetch depth 4 via ring buf[4][row][word]; ring index is compile-time.
__global__ void __launch_bounds__(512, 1) mdlstm_rec_kernel(
    const float* __restrict__ uf, const float* __restrict__ ui,
    const float* __restrict__ uo, const float* __restrict__ uc,
    float* __restrict__ out)
{
    __shared__ float sh_s[4][16][32];
    __shared__ float sh_h[4][16][32];
    __shared__ int   ready[16];

    const int lane = threadIdx.x & 31;
    const int w    = threadIdx.x >> 5;     // 0..15
    const int b    = blockIdx.x >> 2;
    const int og   = blockIdx.x & 3;
    const int o    = og * 32 + lane;

    if (threadIdx.x < 16) ready[threadIdx.x] = -1;
    __syncthreads();
    const uint32_t raddr  = smem_u32(ready);
    const uint32_t r_prev = raddr + 4u * (uint32_t)(w - 1);
    const uint32_t r_next = raddr + 4u * (uint32_t)(w + 1);
    const uint32_t r_self = raddr + 4u * (uint32_t)w;

    UC u;
    u.uf00 = uf[o];        u.uf01 = uf[128 + o];
    u.uf10 = uf[256 + o];  u.uf11 = uf[384 + o];
    u.ui0  = ui[o];        u.ui1  = ui[128 + o];
    u.uo0  = uo[o];        u.uo1  = uo[128 + o];
    u.uc0  = uc[o];        u.uc1  = uc[128 + o];

    const uint32_t* preb = g_pk + (size_t)b * NPW + o;
    float* outb = out + b * 128 + o;

    // per-row col-0 bases
    const uint32_t* pbase[4];
    float* obase[4];
#pragma unroll
    for (int j = 0; j < 4; j++) {
        int r = 4 * w + j;
        pbase[j] = preb + (size_t)(r * 64) * CSTRIDE;
        obase[j] = outb + (size_t)(r * 64) * 4096;
    }

    // ring buffer: buf[slot][row][word]
    uint32_t buf[4][4][3];
#pragma unroll
    for (int p = 0; p < 4; p++) {
#pragma unroll
        for (int j = 0; j < 4; j++) {
            int col = p - j; col = col < 0 ? 0 : col;   // <=63 always here
            const uint32_t* q = pbase[j] + (size_t)col * CSTRIDE;
            buf[p][j][0] = __ldg(q);
            buf[p][j][1] = __ldg(q + 128);
            buf[p][j][2] = __ldg(q + 256);
        }
    }

    float sj[4] = {0.f, 0.f, 0.f, 0.f};
    float hj[4] = {0.f, 0.f, 0.f, 0.f};

#define REC_BODY(S, SLOT)                                                     \
    {                                                                         \
        const int s = (S);                                                    \
        /* snapshot previous-step values (up-neighbors for rows 1..3) */      \
        float os0 = sj[0], oh0 = hj[0];                                       \
        float os1 = sj[1], oh1 = hj[1];                                       \
        float os2 = sj[2], oh2 = hj[2];                                       \
        /* row 0 */                                                           \
        if (s <= 63) {                                                        \
            float sup, hup;                                                   \
            if (w == 0) { sup = 0.f; hup = 0.f; }                             \
            else {                                                            \
                const int need = s + 3;                                       \
                int v;                                                        \
                do {                                                          \
                    asm volatile("ld.acquire.cta.shared.b32 %0, [%1];"        \
                                 : "=r"(v) : "r"(r_prev) : "memory");         \
                } while (v < need);                                           \
                sup = sh_s[(s + 3) & 3][w - 1][lane];                         \
                hup = sh_h[(s + 3) & 3][w - 1][lane];                         \
            }                                                                 \
            float sv, hv;                                                     \
            cell_w(buf[SLOT][0], u, hup, hj[0], sup, sj[0], sv, hv);          \
            obase[0][(size_t)s * 4096] = sv;                                  \
            sj[0] = sv; hj[0] = hv;                                           \
        }                                                                     \
        /* rows 1..3 */                                                       \
        if (s >= 1 && s <= 64) {                                              \
            float sv, hv;                                                     \
            cell_w(buf[SLOT][1], u, oh0, hj[1], os0, sj[1], sv, hv);          \
            obase[1][(size_t)(s - 1) * 4096] = sv;                            \
            sj[1] = sv; hj[1] = hv;                                           \
        }                                                                     \
        if (s >= 2 && s <= 65) {                                              \
            float sv, hv;                                                     \
            cell_w(buf[SLOT][2], u, oh1, hj[2], os1, sj[2], sv, hv);          \
            obase[2][(size_t)(s - 2) * 4096] = sv;                            \
            sj[2] = sv; hj[2] = hv;                                           \
        }                                                                     \
        if (s >= 3 && s <= 66) {                                              \
            float sv, hv;                                                     \
            cell_w(buf[SLOT][3], u, oh2, hj[3], os2, sj[3], sv, hv);          \
            obase[3][(size_t)(s - 3) * 4096] = sv;                            \
            sj[3] = sv; hj[3] = hv;                                           \
            if (w < 15) {                                                     \
                /* back-pressure for slot reuse (depth-4 ring) */             \
                const int needc = s - 7;                                      \
                if (needc >= 0) {                                             \
                    int v;                                                    \
                    do {                                                      \
                        asm volatile("ld.acquire.cta.shared.b32 %0, [%1];"    \
                                     : "=r"(v) : "r"(r_next) : "memory");     \
                    } while (v < needc);                                      \
                }                                                             \
                sh_s[SLOT][w][lane] = sv;                                     \
                sh_h[SLOT][w][lane] = hv;                                     \
            }                                                                 \
        }                                                                     \
        /* publish progress */                                                \
        if (lane == 0) {                                                      \
            asm volatile("st.release.cta.shared.b32 [%0], %1;"                \
                         :: "r"(r_self), "r"(s) : "memory");                  \
        }                                                                     \
        /* refill this slot with data for step s+4 */                         \
        _Pragma("unroll")                                                     \
        for (int j = 0; j < 4; j++) {                                         \
            int col = s + 4 - j;                                              \
            col = col < 0 ? 0 : (col > 63 ? 63 : col);                        \
            const uint32_t* q = pbase[j] + (size_t)col * CSTRIDE;             \
            buf[SLOT][j][0] = __ldg(q);                                       \
            buf[SLOT][j][1] = __ldg(q + 128);                                 \
            buf[SLOT][j][2] = __ldg(q + 256);                                 \
        }                                                                     \
    }

#pragma unroll 1
    for (int sb = 0; sb < 68; sb += 4) {
        REC_BODY(sb + 0, 0)
        REC_BODY(sb + 1, 1)
        REC_BODY(sb + 2, 2)
        REC_BODY(sb + 3, 3)
    }
#undef REC_BODY
}

// ================= launcher =================
extern "C" void kernel_launch(void* const* d_in, const int* in_sizes, int n_in,
                              void* d_out, int out_size) {
    (void)in_sizes; (void)n_in; (void)out_size;
    const float* x     = (const float*)d_in[0];
    const float* wf    = (const float*)d_in[1];
    const float* uf    = (const float*)d_in[2];
    const float* biasf = (const float*)d_in[3];
    const float* wi    = (const float*)d_in[4];
    const float* ui    = (const float*)d_in[5];
    const float* biasi = (const float*)d_in[6];
    const float* wo    = (const float*)d_in[7];
    const float* uo    = (const float*)d_in[8];
    const float* biaso = (const float*)d_in[9];
    const float* wc    = (const float*)d_in[10];
    const float* uc    = (const float*)d_in[11];
    const float* biasc = (const float*)d_in[12];
    float* out = (float*)d_out;

    cudaFuncSetAttribute(gemm_pre_hmma,
                         cudaFuncAttributeMaxDynamicSharedMemorySize, SM_TOTAL);
    gemm_pre_hmma<<<1024, 512, SM_TOTAL>>>(
        x, wf, wi, wo, wc, biasf, biasi, biaso, biasc);
    mdlstm_rec_kernel<<<128, 512>>>(uf, ui, uo, uc, out);
}